// round 16
// baseline (speedup 1.0000x reference)
#include <cuda_runtime.h>
#include <math.h>

#define Bv 64
#define Tv 1024
#define Hv 512
#define NCTA 128

// ---------------- device scratch ----------------
// X projections stored TRANSPOSED: X?T[t][j][b] = [(t*512 + j)*64 + b]
__device__ __align__(16) float g_XrT[(size_t)Tv * Hv * Bv];
__device__ __align__(16) float g_XzT[(size_t)Tv * Hv * Bv];
__device__ __align__(16) float g_XhT[(size_t)Tv * Hv * Bv];
__device__ __align__(16) float g_HS [(size_t)Tv * Bv * Hv];  // layer-0 outputs [m][j]
__device__ __align__(16) float g_hT [Hv * Bv];               // hidden state [j][b]
__device__ __align__(16) float g_rhT[Hv * Bv];               // r*h [j][b]
__device__ __align__(16) float g_z  [Hv * Bv];               // z gate [j][b]
__device__ unsigned int g_gbar[4 * 32];                      // per-group counters, 128B apart

__global__ void reset_bar() {
    int i = threadIdx.x;
    if (i < 4 * 32) g_gbar[i] = 0u;
}

// Group-local barrier: 32 CTAs of batch-group g arrive on one counter.
__device__ __forceinline__ void gbar(int g, unsigned int &target) {
    __syncthreads();
    if (threadIdx.x == 0) {
        __threadfence();
        atomicAdd(&g_gbar[g * 32], 1u);
        target += 32;
        while (*(volatile unsigned int *)&g_gbar[g * 32] < target) { }
        __threadfence();
    }
    __syncthreads();
}

typedef unsigned long long u64;

// Packed fp32x2 helpers (Blackwell FFMA2 via PTX)
#define FMA2(d, a, b) asm("fma.rn.f32x2 %0, %1, %2, %0;" : "+l"(d) : "l"(a), "l"(b))
#define ADD2(d, a)    asm("add.rn.f32x2 %0, %0, %1;"     : "+l"(d) : "l"(a))
#define DUP2(d, f)    asm("mov.b64 %0, {%1, %1};"        : "=l"(d) : "f"(f))
#define CP16(dst, src) asm volatile("cp.async.cg.shared.global [%0], [%1], 16;" \
                                    :: "r"(dst), "l"(src))

__device__ __forceinline__ float fsig(float x) { return 1.0f / (1.0f + __expf(-x)); }

// ---------------- pre-projection GEMM (128x64 tile, cp.async 2-stage) -------
// k-major tiles (cp.async-native layout), per-k-quad float4 reads:
// 12 LDS.128 per 128 FFMA. Accumulation order = k-ascending (bitwise == R13).
template <int GATHER>
__global__ void __launch_bounds__(256) xproj_kernel(
    const float *__restrict__ emb, const int *__restrict__ tokens,
    const float *__restrict__ Wr, const float *__restrict__ Wz,
    const float *__restrict__ Wh,
    const float *__restrict__ br, const float *__restrict__ bz,
    const float *__restrict__ bh,
    int K, int ldW)
{
    __shared__ __align__(16) float As[2][128 * 20];   // [buf][m][k(16,+4 pad)]
    __shared__ __align__(16) float Bs[2][64 * 20];    // [buf][j][k]
    __shared__ const float *rowp[128];
    __shared__ const float *colp[64];

    const int tid = threadIdx.x;
    const int m0 = blockIdx.x * 128;
    const int j0 = blockIdx.y * 64;

    if (tid < 128) {
        int m = m0 + tid;
        if (GATHER) {
            int b = m & 63, t = m >> 6;
            rowp[tid] = emb + (size_t)tokens[b * Tv + t] * 256;
        } else {
            rowp[tid] = g_HS + (size_t)m * Hv;
        }
    } else if (tid < 192) {
        int j = j0 + tid - 128;
        const float *w;
        if (j < 512)       w = Wr + (size_t)j * ldW;
        else if (j < 1024) w = Wz + (size_t)(j - 512) * ldW;
        else               w = Wh + (size_t)(j - 1024) * ldW;
        colp[tid - 128] = w;
    }
    __syncthreads();

#define XSTAGE(buf, k0) do {                                                   \
    _Pragma("unroll")                                                          \
    for (int i_ = 0; i_ < 2; i_++) {                                           \
        int op_ = tid + i_ * 256;                                              \
        int r_ = op_ >> 2, q_ = op_ & 3;                                       \
        CP16((unsigned)__cvta_generic_to_shared(&As[buf][r_ * 20 + q_ * 4]),   \
             rowp[r_] + (k0) + q_ * 4);                                        \
    }                                                                          \
    {                                                                          \
        int r_ = tid >> 2, q_ = tid & 3;                                       \
        CP16((unsigned)__cvta_generic_to_shared(&Bs[buf][r_ * 20 + q_ * 4]),   \
             colp[r_] + (k0) + q_ * 4);                                        \
    }                                                                          \
    asm volatile("cp.async.commit_group;");                                    \
} while (0)

    const int tx = tid & 15, ty = tid >> 4;
    float acc[8][4];
#pragma unroll
    for (int i = 0; i < 8; i++)
#pragma unroll
        for (int j = 0; j < 4; j++) acc[i][j] = 0.0f;

    const int C = K >> 4;
    XSTAGE(0, 0);
    XSTAGE(1, 16);

    for (int c = 0; c < C; c++) {
        if (c + 1 < C) asm volatile("cp.async.wait_group 1;");
        else           asm volatile("cp.async.wait_group 0;");
        __syncthreads();
        const float *ab = As[c & 1];
        const float *bb = Bs[c & 1];
#pragma unroll
        for (int q = 0; q < 4; q++) {
            float4 w4[4];
#pragma unroll
            for (int j = 0; j < 4; j++)
                w4[j] = *(const float4 *)&bb[(tx * 4 + j) * 20 + q * 4];
#pragma unroll
            for (int i = 0; i < 8; i++) {
                float4 a4 = *(const float4 *)&ab[(ty * 8 + i) * 20 + q * 4];
#pragma unroll
                for (int j = 0; j < 4; j++) {
                    acc[i][j] = fmaf(a4.x, w4[j].x, acc[i][j]);
                    acc[i][j] = fmaf(a4.y, w4[j].y, acc[i][j]);
                    acc[i][j] = fmaf(a4.z, w4[j].z, acc[i][j]);
                    acc[i][j] = fmaf(a4.w, w4[j].w, acc[i][j]);
                }
            }
        }
        __syncthreads();
        if (c + 2 < C) XSTAGE(c & 1, (c + 2) * 16);
    }

    float *dst; const float *bias; int jloc;
    if (j0 < 512)       { dst = g_XrT; bias = br; jloc = j0; }
    else if (j0 < 1024) { dst = g_XzT; bias = bz; jloc = j0 - 512; }
    else                { dst = g_XhT; bias = bh; jloc = j0 - 1024; }

    const int c0 = jloc + tx * 4;
    const int t  = (m0 >> 6) + (ty >> 3);
    const int b0 = (ty & 7) * 8;
    const float bsv[4] = {bias[c0], bias[c0 + 1], bias[c0 + 2], bias[c0 + 3]};
#pragma unroll
    for (int jj = 0; jj < 4; jj++) {
        int jg = c0 + jj;
        float4 lo = make_float4(acc[0][jj] + bsv[jj], acc[1][jj] + bsv[jj],
                                acc[2][jj] + bsv[jj], acc[3][jj] + bsv[jj]);
        float4 hi = make_float4(acc[4][jj] + bsv[jj], acc[5][jj] + bsv[jj],
                                acc[6][jj] + bsv[jj], acc[7][jj] + bsv[jj]);
        size_t o = ((size_t)t * 512 + jg) * 64 + b0;
        *(float4 *)&dst[o]     = lo;
        *(float4 *)&dst[o + 4] = hi;
    }
#undef XSTAGE
}

// ---------------- persistent GRU recurrence (4 independent batch groups) -----
// (byte-identical to the proven R13 kernel)
#define SM_W1    0          /* [k][32] stride 36 : 18432 f */
#define SM_W2    18432      /* [k][16] stride 20 : 10240 f */
#define SM_HST   28672      /* [k][16] stride 20 : 10240 f */
#define SM_SRED  38912      /* 16 x 260 u64 = 8320 f */
#define SM_SOUT  47232      /* 256 u64 = 512 f */
#define SM_HSAVE 47744      /* 256 f */
#define SM_XP1   48000      /* phase-1 X slice: 32x16 = 512 f */
#define SM_XP2   48512      /* phase-2 Xh slice: 16x16 = 256 f */
#define SM_ZP    48768      /* phase-2 z slice : 16x16 = 256 f */
#define SM_TOT_FLOATS 49024 /* 196096 bytes */
#define SRED_PITCH 260

__global__ void __launch_bounds__(256) gru_rec_kernel(
    const float *__restrict__ Wr, const float *__restrict__ Wz,
    const float *__restrict__ Wh,
    int D, int ldW, int store_hs)
{
    extern __shared__ __align__(16) float smem[];
    float *w1    = smem + SM_W1;
    float *w2    = smem + SM_W2;
    float *hst   = smem + SM_HST;
    u64   *sred  = (u64 *)(smem + SM_SRED);
    u64   *sout  = (u64 *)(smem + SM_SOUT);
    float *hsave = smem + SM_HSAVE;
    float *xp1   = smem + SM_XP1;
    float *xp2   = smem + SM_XP2;
    float *zp    = smem + SM_ZP;

    const int tid = threadIdx.x;
    const int cid = blockIdx.x;
    const int g   = cid >> 5;          // batch group 0..3
    const int cg  = cid & 31;          // col group   0..31
    const int JA0 = cg * 32;           // phase-1 col base (0..1023)
    const int JB0 = cg * 16;           // phase-2 col base (0..511)
    const int B0  = g * 16;            // batch base

    for (int e = tid; e < 32 * 512; e += 256) {
        int k = e & 511, col = e >> 9;
        int jg = JA0 + col;
        const float *row = (jg < 512) ? (Wr + (size_t)jg * ldW)
                                      : (Wz + (size_t)(jg - 512) * ldW);
        w1[k * 36 + col] = row[D + k];
    }
    for (int e = tid; e < 16 * 512; e += 256) {
        int k = e & 511, col = e >> 9;
        w2[k * 20 + col] = Wh[(size_t)(JB0 + col) * ldW + D + k];
    }
    {
        int idx = cg * 256 + tid;
        int j = idx >> 4, bb = idx & 15;
        __stcg(&g_hT[j * 64 + B0 + bb], 0.0f);
    }
    unsigned int target = 0;
    gbar(g, target);

    const int ks1 = tid >> 4, slab1 = tid & 15;
    const int colsub1 = slab1 >> 1, bsub1 = slab1 & 1;
    const int ks2 = tid >> 3, slab2 = tid & 7;
    const int colsub2 = slab2 >> 1, bsub2 = slab2 & 1;

    for (int t = 0; t < Tv; t++) {
        const size_t xoff = (size_t)t * 32768;        // t*512*64

        // ================= PHASE 1: rz = h @ W1^T =================
        {
#pragma unroll
            for (int it = 0; it < 4; it++) {          // rows 0..255
                int q = tid + it * 256;
                int row = q >> 2, quad = q & 3;
                CP16((unsigned)__cvta_generic_to_shared(hst + row * 20 + quad * 4),
                     g_hT + row * 64 + B0 + quad * 4);
            }
            asm volatile("cp.async.commit_group;");
#pragma unroll
            for (int it = 4; it < 8; it++) {          // rows 256..511
                int q = tid + it * 256;
                int row = q >> 2, quad = q & 3;
                CP16((unsigned)__cvta_generic_to_shared(hst + row * 20 + quad * 4),
                     g_hT + row * 64 + B0 + quad * 4);
            }
            asm volatile("cp.async.commit_group;");
            if (tid < 128) {                          // X slice (Xr or Xz)
                int jl = tid >> 2, q = tid & 3;
                const float *src = (JA0 < 512)
                    ? (g_XrT + xoff + (size_t)(JA0 + jl) * 64 + B0 + q * 4)
                    : (g_XzT + xoff + (size_t)(JA0 - 512 + jl) * 64 + B0 + q * 4);
                CP16((unsigned)__cvta_generic_to_shared(xp1 + jl * 16 + q * 4), src);
            }
            asm volatile("cp.async.commit_group;");

            u64 a[16];
#pragma unroll
            for (int i = 0; i < 16; i++) a[i] = 0;
            const float *hp = hst + ks1 * 20 + bsub1 * 8;
            const float *wp = w1 + ks1 * 36 + colsub1 * 4;
            asm volatile("cp.async.wait_group 2;");
            __syncthreads();
#pragma unroll
            for (int half = 0; half < 2; half++) {
#pragma unroll 4
                for (int i = 0; i < 16; i++) {        // k = half*256 + i*16 + ks1
                    ulonglong2 h01 = *(const ulonglong2 *)hp;
                    ulonglong2 h23 = *(const ulonglong2 *)(hp + 4);
                    float4 wf = *(const float4 *)wp;
                    u64 wd;
                    DUP2(wd, wf.x);
                    FMA2(a[0], h01.x, wd); FMA2(a[1], h01.y, wd);
                    FMA2(a[2], h23.x, wd); FMA2(a[3], h23.y, wd);
                    DUP2(wd, wf.y);
                    FMA2(a[4], h01.x, wd); FMA2(a[5], h01.y, wd);
                    FMA2(a[6], h23.x, wd); FMA2(a[7], h23.y, wd);
                    DUP2(wd, wf.z);
                    FMA2(a[8],  h01.x, wd); FMA2(a[9],  h01.y, wd);
                    FMA2(a[10], h23.x, wd); FMA2(a[11], h23.y, wd);
                    DUP2(wd, wf.w);
                    FMA2(a[12], h01.x, wd); FMA2(a[13], h01.y, wd);
                    FMA2(a[14], h23.x, wd); FMA2(a[15], h23.y, wd);
                    hp += 320; wp += 576;
                }
                if (half == 0) {
                    asm volatile("cp.async.wait_group 1;");
                    __syncthreads();
                }
            }
#pragma unroll
            for (int i = 0; i < 16; i++)
                sred[i * SRED_PITCH + tid] = a[i];
            __syncthreads();
            {   // 16-way ksplit reduction
                int slab = tid & 15, ii = tid >> 4;
                u64 s = sred[ii * SRED_PITCH + slab];
#pragma unroll
                for (int ks = 1; ks < 16; ks++)
                    ADD2(s, sred[ii * SRED_PITCH + ks * 16 + slab]);
                sout[slab * 16 + ii] = s;
            }
            hsave[tid] = hst[(JB0 + (tid >> 4)) * 20 + (tid & 15)];
            asm volatile("cp.async.wait_group 0;");
            __syncthreads();
#pragma unroll
            for (int rep = 0; rep < 2; rep++) {
                int e = tid + rep * 256;
                int jl = e >> 4, bb = e & 15;
                int slab = ((jl >> 2) << 1) | (bb >> 3);
                int ii = (jl & 3) * 4 + ((bb & 7) >> 1);
                float val = ((const float *)sout)[(slab * 16 + ii) * 2 + (bb & 1)];
                int J = JA0 + jl, bglob = B0 + bb;
                float v = val + xp1[jl * 16 + bb];
                if (J < 512) {
                    float r = fsig(v);
                    __stcg(&g_rhT[J * 64 + bglob], r * hst[J * 20 + bb]);
                } else {
                    __stcg(&g_z[(J - 512) * 64 + bglob], fsig(v));
                }
            }
        }
        gbar(g, target);

        // ================= PHASE 2: hn = rh @ Wh^T -> update =================
        {
#pragma unroll
            for (int it = 0; it < 4; it++) {
                int q = tid + it * 256;
                int row = q >> 2, quad = q & 3;
                CP16((unsigned)__cvta_generic_to_shared(hst + row * 20 + quad * 4),
                     g_rhT + row * 64 + B0 + quad * 4);
            }
            asm volatile("cp.async.commit_group;");
#pragma unroll
            for (int it = 4; it < 8; it++) {
                int q = tid + it * 256;
                int row = q >> 2, quad = q & 3;
                CP16((unsigned)__cvta_generic_to_shared(hst + row * 20 + quad * 4),
                     g_rhT + row * 64 + B0 + quad * 4);
            }
            asm volatile("cp.async.commit_group;");
            if (tid < 64) {                           // Xh slice
                int jl = tid >> 2, q = tid & 3;
                CP16((unsigned)__cvta_generic_to_shared(xp2 + jl * 16 + q * 4),
                     g_XhT + xoff + (size_t)(JB0 + jl) * 64 + B0 + q * 4);
            } else if (tid < 128) {                   // z slice
                int e = tid - 64;
                int jl = e >> 2, q = e & 3;
                CP16((unsigned)__cvta_generic_to_shared(zp + jl * 16 + q * 4),
                     g_z + (size_t)(JB0 + jl) * 64 + B0 + q * 4);
            }
            asm volatile("cp.async.commit_group;");

            u64 a[16];
#pragma unroll
            for (int i = 0; i < 16; i++) a[i] = 0;
            const float *hp = hst + ks2 * 20 + bsub2 * 8;
            const float *wp = w2 + ks2 * 20 + colsub2 * 4;
            asm volatile("cp.async.wait_group 2;");
            __syncthreads();
#pragma unroll
            for (int half = 0; half < 2; half++) {
#pragma unroll 4
                for (int i = 0; i < 8; i++) {         // k = half*256 + i*32 + ks2
                    ulonglong2 h01 = *(const ulonglong2 *)hp;
                    ulonglong2 h23 = *(const ulonglong2 *)(hp + 4);
                    float4 wf = *(const float4 *)wp;
                    u64 wd;
                    DUP2(wd, wf.x);
                    FMA2(a[0], h01.x, wd); FMA2(a[1], h01.y, wd);
                    FMA2(a[2], h23.x, wd); FMA2(a[3], h23.y, wd);
                    DUP2(wd, wf.y);
                    FMA2(a[4], h01.x, wd); FMA2(a[5], h01.y, wd);
                    FMA2(a[6], h23.x, wd); FMA2(a[7], h23.y, wd);
                    DUP2(wd, wf.z);
                    FMA2(a[8],  h01.x, wd); FMA2(a[9],  h01.y, wd);
                    FMA2(a[10], h23.x, wd); FMA2(a[11], h23.y, wd);
                    DUP2(wd, wf.w);
                    FMA2(a[12], h01.x, wd); FMA2(a[13], h01.y, wd);
                    FMA2(a[14], h23.x, wd); FMA2(a[15], h23.y, wd);
                    hp += 640; wp += 640;
                }
                if (half == 0) {
                    asm volatile("cp.async.wait_group 1;");
                    __syncthreads();
                }
            }
#pragma unroll
            for (int i = 0; i < 16; i++)
                sred[i * SRED_PITCH + tid] = a[i];
            __syncthreads();
            if (tid < 128) {   // 32-way ksplit reduction
                int slab = tid & 7, ii = tid >> 3;
                u64 s = sred[ii * SRED_PITCH + slab];
#pragma unroll
                for (int ks = 1; ks < 32; ks++)
                    ADD2(s, sred[ii * SRED_PITCH + ks * 8 + slab]);
                sout[slab * 16 + ii] = s;
            }
            asm volatile("cp.async.wait_group 0;");
            __syncthreads();
            {
                int jl = tid & 15, bb = tid >> 4;
                int slab = ((jl >> 2) << 1) | (bb >> 3);
                int ii = (jl & 3) * 4 + ((bb & 7) >> 1);
                float val = ((const float *)sout)[(slab * 16 + ii) * 2 + (bb & 1)];
                int J = JB0 + jl, bglob = B0 + bb;
                float sh = val + xp2[jl * 16 + bb];
                float ht = tanhf(sh);
                float z  = zp[jl * 16 + bb];
                float h  = hsave[jl * 16 + bb];
                float hn = h + z * (ht - h);
                __stcg(&g_hT[J * 64 + bglob], hn);
                if (store_hs)
                    g_HS[((size_t)t * 64 + bglob) * 512 + J] = hn;
            }
        }
        gbar(g, target);
    }
}

// ---------------- final FC ----------------
__global__ void fc_kernel(const float *__restrict__ fcW,
                          const float *__restrict__ fcb,
                          float *__restrict__ out)
{
    int b = threadIdx.x >> 1, c = threadIdx.x & 1;
    float s = 0.0f;
    for (int j = 0; j < Hv; j++)
        s = fmaf(g_hT[j * 64 + b], fcW[c * Hv + j], s);
    out[b * 2 + c] = s + fcb[c];
}

// ---------------- launch ----------------
extern "C" void kernel_launch(void* const* d_in, const int* in_sizes, int n_in,
                              void* d_out, int out_size) {
    const int   *tokens = (const int *)d_in[0];
    const float *emb = (const float *)d_in[1];
    const float *Wr0 = (const float *)d_in[2];
    const float *br0 = (const float *)d_in[3];
    const float *Wz0 = (const float *)d_in[4];
    const float *bz0 = (const float *)d_in[5];
    const float *Wh0 = (const float *)d_in[6];
    const float *bh0 = (const float *)d_in[7];
    const float *Wr1 = (const float *)d_in[8];
    const float *br1 = (const float *)d_in[9];
    const float *Wz1 = (const float *)d_in[10];
    const float *bz1 = (const float *)d_in[11];
    const float *Wh1 = (const float *)d_in[12];
    const float *bh1 = (const float *)d_in[13];
    const float *fcW = (const float *)d_in[14];
    const float *fcb = (const float *)d_in[15];
    float *out = (float *)d_out;

    static int smem_set = 0;
    if (!smem_set) {
        cudaFuncSetAttribute(gru_rec_kernel,
                             cudaFuncAttributeMaxDynamicSharedMemorySize,
                             SM_TOT_FLOATS * 4);
        smem_set = 1;
    }

    dim3 gx(512, 24);

    // Layer 0
    xproj_kernel<1><<<gx, 256>>>(emb, tokens, Wr0, Wz0, Wh0, br0, bz0, bh0,
                                 256, 768);
    reset_bar<<<1, 128>>>();
    gru_rec_kernel<<<NCTA, 256, SM_TOT_FLOATS * 4>>>(Wr0, Wz0, Wh0, 256, 768, 1);

    // Layer 1
    xproj_kernel<0><<<gx, 256>>>(nullptr, nullptr, Wr1, Wz1, Wh1, br1, bz1, bh1,
                                 512, 1024);
    reset_bar<<<1, 128>>>();
    gru_rec_kernel<<<NCTA, 256, SM_TOT_FLOATS * 4>>>(Wr1, Wz1, Wh1, 512, 1024, 0);

    // Classifier
    fc_kernel<<<1, 128>>>(fcW, fcb, out);
}

// round 17
// speedup vs baseline: 1.2050x; 1.2050x over previous
#include <cuda_runtime.h>
#include <math.h>

#define Bv 64
#define Tv 1024
#define Hv 512
#define NCTA 128

// ---------------- device scratch ----------------
// X projections stored TRANSPOSED: X?T[t][j][b] = [(t*512 + j)*64 + b]
__device__ __align__(16) float g_XrT[(size_t)Tv * Hv * Bv];
__device__ __align__(16) float g_XzT[(size_t)Tv * Hv * Bv];
__device__ __align__(16) float g_XhT[(size_t)Tv * Hv * Bv];
__device__ __align__(16) float g_HS [(size_t)Tv * Bv * Hv];  // layer-0 outputs [m][j]
__device__ __align__(16) float g_hT [Hv * Bv];               // hidden state [j][b]
__device__ __align__(16) float g_rhT[Hv * Bv];               // r*h [j][b]
__device__ __align__(16) float g_z  [Hv * Bv];               // z gate [j][b]
__device__ unsigned int g_gbar[4 * 32];                      // per-group counters, 128B apart

__global__ void reset_bar() {
    int i = threadIdx.x;
    if (i < 4 * 32) g_gbar[i] = 0u;
}

// Group-local barrier: 32 CTAs of batch-group g arrive on one counter.
// release-arrive / acquire-poll (no full membar needed).
__device__ __forceinline__ void gbar(int g, unsigned int &target) {
    __syncthreads();
    if (threadIdx.x == 0) {
        asm volatile("red.release.gpu.global.add.u32 [%0], %1;"
                     :: "l"(&g_gbar[g * 32]), "r"(1u) : "memory");
        target += 32;
        unsigned int v;
        do {
            asm volatile("ld.acquire.gpu.global.u32 %0, [%1];"
                         : "=r"(v) : "l"(&g_gbar[g * 32]) : "memory");
        } while (v < target);
    }
    __syncthreads();
}

typedef unsigned long long u64;

// Packed fp32x2 helpers (Blackwell FFMA2 via PTX)
#define FMA2(d, a, b) asm("fma.rn.f32x2 %0, %1, %2, %0;" : "+l"(d) : "l"(a), "l"(b))
#define ADD2(d, a)    asm("add.rn.f32x2 %0, %0, %1;"     : "+l"(d) : "l"(a))
#define DUP2(d, f)    asm("mov.b64 %0, {%1, %1};"        : "=l"(d) : "f"(f))
#define CP16(dst, src) asm volatile("cp.async.cg.shared.global [%0], [%1], 16;" \
                                    :: "r"(dst), "l"(src))

__device__ __forceinline__ float fsig(float x) { return 1.0f / (1.0f + __expf(-x)); }

// ---------------- pre-projection GEMM (R13-proven: 128x64 tile, 8x4 fmaf) ----
template <int GATHER>
__global__ void __launch_bounds__(256) xproj_kernel(
    const float *__restrict__ emb, const int *__restrict__ tokens,
    const float *__restrict__ Wr, const float *__restrict__ Wz,
    const float *__restrict__ Wh,
    const float *__restrict__ br, const float *__restrict__ bz,
    const float *__restrict__ bh,
    int K, int ldW)
{
    __shared__ __align__(16) float As[16][132];
    __shared__ __align__(16) float Bs[16][68];
    __shared__ const float *rowp[128];
    __shared__ const float *colp[64];

    const int tid = threadIdx.x;
    const int m0 = blockIdx.x * 128;
    const int j0 = blockIdx.y * 64;

    if (tid < 128) {
        int m = m0 + tid;
        if (GATHER) {
            int b = m & 63, t = m >> 6;
            rowp[tid] = emb + (size_t)tokens[b * Tv + t] * 256;
        } else {
            rowp[tid] = g_HS + (size_t)m * Hv;
        }
    } else if (tid < 192) {
        int j = j0 + tid - 128;
        const float *w;
        if (j < 512)       w = Wr + (size_t)j * ldW;
        else if (j < 1024) w = Wz + (size_t)(j - 512) * ldW;
        else               w = Wh + (size_t)(j - 1024) * ldW;
        colp[tid - 128] = w;
    }
    __syncthreads();

    const int tx = tid & 15, ty = tid >> 4;
    float acc[8][4];
#pragma unroll
    for (int i = 0; i < 8; i++)
#pragma unroll
        for (int j = 0; j < 4; j++) acc[i][j] = 0.0f;

    for (int k0 = 0; k0 < K; k0 += 16) {
#pragma unroll
        for (int i = 0; i < 2; i++) {
            int id = tid + i * 256;
            int kk = id & 3, r = id >> 2;
            float4 v = *(const float4 *)(rowp[r] + k0 + kk * 4);
            As[kk * 4 + 0][r] = v.x; As[kk * 4 + 1][r] = v.y;
            As[kk * 4 + 2][r] = v.z; As[kk * 4 + 3][r] = v.w;
        }
        {
            int kk = tid & 3, jj = tid >> 2;
            float4 v = *(const float4 *)(colp[jj] + k0 + kk * 4);
            Bs[kk * 4 + 0][jj] = v.x; Bs[kk * 4 + 1][jj] = v.y;
            Bs[kk * 4 + 2][jj] = v.z; Bs[kk * 4 + 3][jj] = v.w;
        }
        __syncthreads();
#pragma unroll
        for (int k = 0; k < 16; k++) {
            float a[8], w[4];
            *(float4 *)&a[0] = *(const float4 *)&As[k][ty * 8];
            *(float4 *)&a[4] = *(const float4 *)&As[k][ty * 8 + 4];
            *(float4 *)&w[0] = *(const float4 *)&Bs[k][tx * 4];
#pragma unroll
            for (int i = 0; i < 8; i++)
#pragma unroll
                for (int j = 0; j < 4; j++)
                    acc[i][j] = fmaf(a[i], w[j], acc[i][j]);
        }
        __syncthreads();
    }

    float *dst; const float *bias; int jloc;
    if (j0 < 512)       { dst = g_XrT; bias = br; jloc = j0; }
    else if (j0 < 1024) { dst = g_XzT; bias = bz; jloc = j0 - 512; }
    else                { dst = g_XhT; bias = bh; jloc = j0 - 1024; }

    const int c0 = jloc + tx * 4;
    const int t  = (m0 >> 6) + (ty >> 3);
    const int b0 = (ty & 7) * 8;
    const float bsv[4] = {bias[c0], bias[c0 + 1], bias[c0 + 2], bias[c0 + 3]};
#pragma unroll
    for (int jj = 0; jj < 4; jj++) {
        int jg = c0 + jj;
        float4 lo = make_float4(acc[0][jj] + bsv[jj], acc[1][jj] + bsv[jj],
                                acc[2][jj] + bsv[jj], acc[3][jj] + bsv[jj]);
        float4 hi = make_float4(acc[4][jj] + bsv[jj], acc[5][jj] + bsv[jj],
                                acc[6][jj] + bsv[jj], acc[7][jj] + bsv[jj]);
        size_t o = ((size_t)t * 512 + jg) * 64 + b0;
        *(float4 *)&dst[o]     = lo;
        *(float4 *)&dst[o + 4] = hi;
    }
}

// ---------------- persistent GRU recurrence (4 independent batch groups) -----
// 128 CTAs = 4 groups x 32 CTAs. Group g owns batches g*16..+16 and runs its
// own time loop with a group-local barrier (no cross-group sync at all).
// SMEM float offsets:
#define SM_W1    0          /* [k][32] stride 36 : 18432 f */
#define SM_W2    18432      /* [k][16] stride 20 : 10240 f */
#define SM_HST   28672      /* [k][16] stride 20 : 10240 f */
#define SM_SRED  38912      /* 16 x 260 u64 = 8320 f */
#define SM_SOUT  47232      /* 256 u64 = 512 f */
#define SM_HSAVE 47744      /* 256 f */
#define SM_XP1   48000      /* phase-1 X slice: 32x16 = 512 f */
#define SM_XP2   48512      /* phase-2 Xh slice: 16x16 = 256 f */
#define SM_ZP    48768      /* phase-2 z slice : 16x16 = 256 f */
#define SM_TOT_FLOATS 49024 /* 196096 bytes */
#define SRED_PITCH 260

__global__ void __launch_bounds__(256) gru_rec_kernel(
    const float *__restrict__ Wr, const float *__restrict__ Wz,
    const float *__restrict__ Wh,
    int D, int ldW, int store_hs)
{
    extern __shared__ __align__(16) float smem[];
    float *w1    = smem + SM_W1;
    float *w2    = smem + SM_W2;
    float *hst   = smem + SM_HST;
    u64   *sred  = (u64 *)(smem + SM_SRED);
    u64   *sout  = (u64 *)(smem + SM_SOUT);
    float *hsave = smem + SM_HSAVE;
    float *xp1   = smem + SM_XP1;
    float *xp2   = smem + SM_XP2;
    float *zp    = smem + SM_ZP;

    const int tid = threadIdx.x;
    const int cid = blockIdx.x;
    const int g   = cid >> 5;          // batch group 0..3
    const int cg  = cid & 31;          // col group   0..31
    const int JA0 = cg * 32;           // phase-1 col base (0..1023)
    const int JB0 = cg * 16;           // phase-2 col base (0..511)
    const int B0  = g * 16;            // batch base

    // ---- one-time weight preload (compact, padded rows) ----
    for (int e = tid; e < 32 * 512; e += 256) {
        int k = e & 511, col = e >> 9;
        int jg = JA0 + col;
        const float *row = (jg < 512) ? (Wr + (size_t)jg * ldW)
                                      : (Wz + (size_t)(jg - 512) * ldW);
        w1[k * 36 + col] = row[D + k];
    }
    for (int e = tid; e < 16 * 512; e += 256) {
        int k = e & 511, col = e >> 9;
        w2[k * 20 + col] = Wh[(size_t)(JB0 + col) * ldW + D + k];
    }
    // h0 = 0: group-local init
    {
        int idx = cg * 256 + tid;
        int j = idx >> 4, bb = idx & 15;
        __stcg(&g_hT[j * 64 + B0 + bb], 0.0f);
    }
    unsigned int target = 0;
    gbar(g, target);

    // phase-1 roles: ks1 in [0,16), slab = colsub1(8) x bsub1(2)
    const int ks1 = tid >> 4, slab1 = tid & 15;
    const int colsub1 = slab1 >> 1, bsub1 = slab1 & 1;
    // phase-2 roles: ks2 in [0,32), slab = colsub2(4) x bsub2(2)
    const int ks2 = tid >> 3, slab2 = tid & 7;
    const int colsub2 = slab2 >> 1, bsub2 = slab2 & 1;

    for (int t = 0; t < Tv; t++) {
        const size_t xoff = (size_t)t * 32768;        // t*512*64

        // ================= PHASE 1: rz = h @ W1^T =================
        {
#pragma unroll
            for (int it = 0; it < 4; it++) {          // rows 0..255
                int q = tid + it * 256;
                int row = q >> 2, quad = q & 3;
                CP16((unsigned)__cvta_generic_to_shared(hst + row * 20 + quad * 4),
                     g_hT + row * 64 + B0 + quad * 4);
            }
            asm volatile("cp.async.commit_group;");
#pragma unroll
            for (int it = 4; it < 8; it++) {          // rows 256..511
                int q = tid + it * 256;
                int row = q >> 2, quad = q & 3;
                CP16((unsigned)__cvta_generic_to_shared(hst + row * 20 + quad * 4),
                     g_hT + row * 64 + B0 + quad * 4);
            }
            asm volatile("cp.async.commit_group;");
            if (tid < 128) {                          // X slice (Xr or Xz)
                int jl = tid >> 2, q = tid & 3;
                const float *src = (JA0 < 512)
                    ? (g_XrT + xoff + (size_t)(JA0 + jl) * 64 + B0 + q * 4)
                    : (g_XzT + xoff + (size_t)(JA0 - 512 + jl) * 64 + B0 + q * 4);
                CP16((unsigned)__cvta_generic_to_shared(xp1 + jl * 16 + q * 4), src);
            }
            asm volatile("cp.async.commit_group;");

            u64 a[16];
#pragma unroll
            for (int i = 0; i < 16; i++) a[i] = 0;
            const float *hp = hst + ks1 * 20 + bsub1 * 8;
            const float *wp = w1 + ks1 * 36 + colsub1 * 4;
            asm volatile("cp.async.wait_group 2;");
            __syncthreads();
#pragma unroll
            for (int half = 0; half < 2; half++) {
#pragma unroll 4
                for (int i = 0; i < 16; i++) {        // k = half*256 + i*16 + ks1
                    ulonglong2 h01 = *(const ulonglong2 *)hp;
                    ulonglong2 h23 = *(const ulonglong2 *)(hp + 4);
                    float4 wf = *(const float4 *)wp;
                    u64 wd;
                    DUP2(wd, wf.x);
                    FMA2(a[0], h01.x, wd); FMA2(a[1], h01.y, wd);
                    FMA2(a[2], h23.x, wd); FMA2(a[3], h23.y, wd);
                    DUP2(wd, wf.y);
                    FMA2(a[4], h01.x, wd); FMA2(a[5], h01.y, wd);
                    FMA2(a[6], h23.x, wd); FMA2(a[7], h23.y, wd);
                    DUP2(wd, wf.z);
                    FMA2(a[8],  h01.x, wd); FMA2(a[9],  h01.y, wd);
                    FMA2(a[10], h23.x, wd); FMA2(a[11], h23.y, wd);
                    DUP2(wd, wf.w);
                    FMA2(a[12], h01.x, wd); FMA2(a[13], h01.y, wd);
                    FMA2(a[14], h23.x, wd); FMA2(a[15], h23.y, wd);
                    hp += 320; wp += 576;
                }
                if (half == 0) {
                    asm volatile("cp.async.wait_group 1;");
                    __syncthreads();
                }
            }
#pragma unroll
            for (int i = 0; i < 16; i++)
                sred[i * SRED_PITCH + tid] = a[i];
            __syncthreads();
            {   // 16-way ksplit reduction
                int slab = tid & 15, ii = tid >> 4;
                u64 s = sred[ii * SRED_PITCH + slab];
#pragma unroll
                for (int ks = 1; ks < 16; ks++)
                    ADD2(s, sred[ii * SRED_PITCH + ks * 16 + slab]);
                sout[slab * 16 + ii] = s;
            }
            hsave[tid] = hst[(JB0 + (tid >> 4)) * 20 + (tid & 15)];
            asm volatile("cp.async.wait_group 0;");
            __syncthreads();
            // epilogue: 512 outputs, 2 per thread (X from SMEM prefetch)
#pragma unroll
            for (int rep = 0; rep < 2; rep++) {
                int e = tid + rep * 256;
                int jl = e >> 4, bb = e & 15;
                int slab = ((jl >> 2) << 1) | (bb >> 3);
                int ii = (jl & 3) * 4 + ((bb & 7) >> 1);
                float val = ((const float *)sout)[(slab * 16 + ii) * 2 + (bb & 1)];
                int J = JA0 + jl, bglob = B0 + bb;
                float v = val + xp1[jl * 16 + bb];
                if (J < 512) {
                    float r = fsig(v);
                    __stcg(&g_rhT[J * 64 + bglob], r * hst[J * 20 + bb]);
                } else {
                    __stcg(&g_z[(J - 512) * 64 + bglob], fsig(v));
                }
            }
        }
        gbar(g, target);

        // ================= PHASE 2: hn = rh @ Wh^T -> update =================
        {
#pragma unroll
            for (int it = 0; it < 4; it++) {
                int q = tid + it * 256;
                int row = q >> 2, quad = q & 3;
                CP16((unsigned)__cvta_generic_to_shared(hst + row * 20 + quad * 4),
                     g_rhT + row * 64 + B0 + quad * 4);
            }
            asm volatile("cp.async.commit_group;");
#pragma unroll
            for (int it = 4; it < 8; it++) {
                int q = tid + it * 256;
                int row = q >> 2, quad = q & 3;
                CP16((unsigned)__cvta_generic_to_shared(hst + row * 20 + quad * 4),
                     g_rhT + row * 64 + B0 + quad * 4);
            }
            asm volatile("cp.async.commit_group;");
            if (tid < 64) {                           // Xh slice
                int jl = tid >> 2, q = tid & 3;
                CP16((unsigned)__cvta_generic_to_shared(xp2 + jl * 16 + q * 4),
                     g_XhT + xoff + (size_t)(JB0 + jl) * 64 + B0 + q * 4);
            } else if (tid < 128) {                   // z slice
                int e = tid - 64;
                int jl = e >> 2, q = e & 3;
                CP16((unsigned)__cvta_generic_to_shared(zp + jl * 16 + q * 4),
                     g_z + (size_t)(JB0 + jl) * 64 + B0 + q * 4);
            }
            asm volatile("cp.async.commit_group;");

            u64 a[16];
#pragma unroll
            for (int i = 0; i < 16; i++) a[i] = 0;
            const float *hp = hst + ks2 * 20 + bsub2 * 8;
            const float *wp = w2 + ks2 * 20 + colsub2 * 4;
            asm volatile("cp.async.wait_group 2;");
            __syncthreads();
#pragma unroll
            for (int half = 0; half < 2; half++) {
#pragma unroll 4
                for (int i = 0; i < 8; i++) {         // k = half*256 + i*32 + ks2
                    ulonglong2 h01 = *(const ulonglong2 *)hp;
                    ulonglong2 h23 = *(const ulonglong2 *)(hp + 4);
                    float4 wf = *(const float4 *)wp;
                    u64 wd;
                    DUP2(wd, wf.x);
                    FMA2(a[0], h01.x, wd); FMA2(a[1], h01.y, wd);
                    FMA2(a[2], h23.x, wd); FMA2(a[3], h23.y, wd);
                    DUP2(wd, wf.y);
                    FMA2(a[4], h01.x, wd); FMA2(a[5], h01.y, wd);
                    FMA2(a[6], h23.x, wd); FMA2(a[7], h23.y, wd);
                    DUP2(wd, wf.z);
                    FMA2(a[8],  h01.x, wd); FMA2(a[9],  h01.y, wd);
                    FMA2(a[10], h23.x, wd); FMA2(a[11], h23.y, wd);
                    DUP2(wd, wf.w);
                    FMA2(a[12], h01.x, wd); FMA2(a[13], h01.y, wd);
                    FMA2(a[14], h23.x, wd); FMA2(a[15], h23.y, wd);
                    hp += 640; wp += 640;
                }
                if (half == 0) {
                    asm volatile("cp.async.wait_group 1;");
                    __syncthreads();
                }
            }
#pragma unroll
            for (int i = 0; i < 16; i++)
                sred[i * SRED_PITCH + tid] = a[i];
            __syncthreads();
            if (tid < 128) {   // 32-way ksplit reduction
                int slab = tid & 7, ii = tid >> 3;
                u64 s = sred[ii * SRED_PITCH + slab];
#pragma unroll
                for (int ks = 1; ks < 32; ks++)
                    ADD2(s, sred[ii * SRED_PITCH + ks * 8 + slab]);
                sout[slab * 16 + ii] = s;
            }
            asm volatile("cp.async.wait_group 0;");
            __syncthreads();
            // epilogue: 256 outputs, 1 per thread (everything from SMEM)
            {
                int jl = tid & 15, bb = tid >> 4;
                int slab = ((jl >> 2) << 1) | (bb >> 3);
                int ii = (jl & 3) * 4 + ((bb & 7) >> 1);
                float val = ((const float *)sout)[(slab * 16 + ii) * 2 + (bb & 1)];
                int J = JB0 + jl, bglob = B0 + bb;
                float sh = val + xp2[jl * 16 + bb];
                float ht = tanhf(sh);
                float z  = zp[jl * 16 + bb];
                float h  = hsave[jl * 16 + bb];
                float hn = h + z * (ht - h);
                __stcg(&g_hT[J * 64 + bglob], hn);
                if (store_hs)
                    g_HS[((size_t)t * 64 + bglob) * 512 + J] = hn;
            }
        }
        gbar(g, target);
    }
}

// ---------------- final FC ----------------
__global__ void fc_kernel(const float *__restrict__ fcW,
                          const float *__restrict__ fcb,
                          float *__restrict__ out)
{
    int b = threadIdx.x >> 1, c = threadIdx.x & 1;
    float s = 0.0f;
    for (int j = 0; j < Hv; j++)
        s = fmaf(g_hT[j * 64 + b], fcW[c * Hv + j], s);
    out[b * 2 + c] = s + fcb[c];
}

// ---------------- launch ----------------
extern "C" void kernel_launch(void* const* d_in, const int* in_sizes, int n_in,
                              void* d_out, int out_size) {
    const int   *tokens = (const int *)d_in[0];
    const float *emb = (const float *)d_in[1];
    const float *Wr0 = (const float *)d_in[2];
    const float *br0 = (const float *)d_in[3];
    const float *Wz0 = (const float *)d_in[4];
    const float *bz0 = (const float *)d_in[5];
    const float *Wh0 = (const float *)d_in[6];
    const float *bh0 = (const float *)d_in[7];
    const float *Wr1 = (const float *)d_in[8];
    const float *br1 = (const float *)d_in[9];
    const float *Wz1 = (const float *)d_in[10];
    const float *bz1 = (const float *)d_in[11];
    const float *Wh1 = (const float *)d_in[12];
    const float *bh1 = (const float *)d_in[13];
    const float *fcW = (const float *)d_in[14];
    const float *fcb = (const float *)d_in[15];
    float *out = (float *)d_out;

    static int smem_set = 0;
    if (!smem_set) {
        cudaFuncSetAttribute(gru_rec_kernel,
                             cudaFuncAttributeMaxDynamicSharedMemorySize,
                             SM_TOT_FLOATS * 4);
        smem_set = 1;
    }

    dim3 gx(512, 24);

    // Layer 0
    xproj_kernel<1><<<gx, 256>>>(emb, tokens, Wr0, Wz0, Wh0, br0, bz0, bh0,
                                 256, 768);
    reset_bar<<<1, 128>>>();
    gru_rec_kernel<<<NCTA, 256, SM_TOT_FLOATS * 4>>>(Wr0, Wz0, Wh0, 256, 768, 1);

    // Layer 1
    xproj_kernel<0><<<gx, 256>>>(nullptr, nullptr, Wr1, Wz1, Wh1, br1, bz1, bh1,
                                 512, 1024);
    reset_bar<<<1, 128>>>();
    gru_rec_kernel<<<NCTA, 256, SM_TOT_FLOATS * 4>>>(Wr1, Wz1, Wh1, 512, 1024, 0);

    // Classifier
    fc_kernel<<<1, 128>>>(fcW, fcb, out);
}